// round 17
// baseline (speedup 1.0000x reference)
#include <cuda_runtime.h>
#include <cstdint>

#define Bt    1024
#define Tt    1000
#define HH    256
#define NBLK  128
#define NTHR  256
#define ICC   88                 // W2/W3 rows cached in SMEM (22 iters of 4)
#define NSTREAM 42               // streamed iters per layer: (256-88)/4
#define PFD   6                  // LDG prefetch depth (rotation)
#define NSMAIN (NSTREAM - PFD)   // 36

using u64 = unsigned long long;

__device__ __forceinline__ u64 ffma2(u64 a, u64 b, u64 c) {
    u64 d; asm("fma.rn.f32x2 %0,%1,%2,%3;" : "=l"(d) : "l"(a), "l"(b), "l"(c)); return d;
}
__device__ __forceinline__ u64 addf2(u64 a, u64 b) {
    u64 d; asm("add.rn.f32x2 %0,%1,%2;" : "=l"(d) : "l"(a), "l"(b)); return d;
}
__device__ __forceinline__ u64 pack2(float x, float y) {
    u64 d; asm("mov.b64 %0,{%1,%2};" : "=l"(d) : "f"(x), "f"(y)); return d;
}
__device__ __forceinline__ float2 unpack2(u64 a) {
    float2 f; asm("mov.b64 {%0,%1},%2;" : "=f"(f.x), "=f"(f.y) : "l"(a)); return f;
}
__device__ __forceinline__ float elu1(float v) { return v > 0.f ? v : (__expf(v) - 1.f); }

#define HROW(i) ((i) * 8 + ((i) >> 2) * 4)

#define OFF_W2   0
#define OFF_W3   22528
#define OFF_HA   45056
#define OFF_HB   47360
#define OFF_H3   49664
#define OFF_W4   51744
#define OFF_INP  53824
#define OFF_RED  53968
#define OFF_ZJ   54224
#define OFF_EVT  54288
#define OFF_B4   54296
#define OFF_TSH  54304
#define SM_FLOATS 54306
#define SM_BYTES  (SM_FLOATS * 4)

// accumulate one weight row given preloaded operands (SMEM-cached w)
__device__ __forceinline__ void accum_ops(ulonglong2 w, ulonglong2 hlo, ulonglong2 hhi,
                                          u64* __restrict__ acc) {
    float2 wl = unpack2(w.x), wh = unpack2(w.y);
    u64 wd0 = pack2(wl.x, wl.x), wd1 = pack2(wl.y, wl.y);
    u64 wd2 = pack2(wh.x, wh.x), wd3 = pack2(wh.y, wh.y);
    acc[0]  = ffma2(hlo.x, wd0, acc[0]);  acc[1]  = ffma2(hlo.y, wd0, acc[1]);
    acc[2]  = ffma2(hhi.x, wd0, acc[2]);  acc[3]  = ffma2(hhi.y, wd0, acc[3]);
    acc[4]  = ffma2(hlo.x, wd1, acc[4]);  acc[5]  = ffma2(hlo.y, wd1, acc[5]);
    acc[6]  = ffma2(hhi.x, wd1, acc[6]);  acc[7]  = ffma2(hhi.y, wd1, acc[7]);
    acc[8]  = ffma2(hlo.x, wd2, acc[8]);  acc[9]  = ffma2(hlo.y, wd2, acc[9]);
    acc[10] = ffma2(hhi.x, wd2, acc[10]); acc[11] = ffma2(hhi.y, wd2, acc[11]);
    acc[12] = ffma2(hlo.x, wd3, acc[12]); acc[13] = ffma2(hlo.y, wd3, acc[13]);
    acc[14] = ffma2(hhi.x, wd3, acc[14]); acc[15] = ffma2(hhi.y, wd3, acc[15]);
}

// accumulate one weight row given preloaded operands (register w from LDG)
__device__ __forceinline__ void accum_rws(float4 wv, ulonglong2 hlo, ulonglong2 hhi,
                                          u64* __restrict__ acc) {
    u64 wd0 = pack2(wv.x, wv.x), wd1 = pack2(wv.y, wv.y);
    u64 wd2 = pack2(wv.z, wv.z), wd3 = pack2(wv.w, wv.w);
    acc[0]  = ffma2(hlo.x, wd0, acc[0]);  acc[1]  = ffma2(hlo.y, wd0, acc[1]);
    acc[2]  = ffma2(hhi.x, wd0, acc[2]);  acc[3]  = ffma2(hhi.y, wd0, acc[3]);
    acc[4]  = ffma2(hlo.x, wd1, acc[4]);  acc[5]  = ffma2(hlo.y, wd1, acc[5]);
    acc[6]  = ffma2(hhi.x, wd1, acc[6]);  acc[7]  = ffma2(hhi.y, wd1, acc[7]);
    acc[8]  = ffma2(hlo.x, wd2, acc[8]);  acc[9]  = ffma2(hlo.y, wd2, acc[9]);
    acc[10] = ffma2(hhi.x, wd2, acc[10]); acc[11] = ffma2(hhi.y, wd2, acc[11]);
    acc[12] = ffma2(hlo.x, wd3, acc[12]); acc[13] = ffma2(hlo.y, wd3, acc[13]);
    acc[14] = ffma2(hhi.x, wd3, acc[14]); acc[15] = ffma2(hhi.y, wd3, acc[15]);
}

// full 256->256 layer: software-pipelined cached rows + L2->register streamed rows
template <bool TO_H3P>
__device__ __forceinline__ void biglayerG(
    const float* __restrict__ wc,
    const float* __restrict__ Wg,
    const float* __restrict__ hsrc, float* __restrict__ hdst,
    int j0q, int kq, int quadg, ulonglong2 bq)
{
    u64 acc[16];
#pragma unroll
    for (int q = 0; q < 16; q++) acc[q] = 0ull;

    const float* wt  = wc + kq * HH + j0q;
    const float* wgx = Wg + (ICC + kq) * HH + j0q;
    const float* ht  = hsrc + kq * 8;

    // LDG rotation prologue (lands during cached loop)
    float4 buf[PFD];
#pragma unroll
    for (int p = 0; p < PFD; p++)
        buf[p] = __ldg((const float4*)(wgx + p * 4 * HH));

    // ---- cached rows: depth-1 software pipeline, 21 iters + peeled last ----
    ulonglong2 wcur = *(const ulonglong2*)wt;
    ulonglong2 hc0  = *(const ulonglong2*)ht;
    ulonglong2 hc1  = *(const ulonglong2*)(ht + 4);
#pragma unroll 3
    for (int n = 0; n < ICC / 4 - 1; n++) {
        ulonglong2 wn  = *(const ulonglong2*)(wt + (n + 1) * 4 * HH);
        ulonglong2 hn0 = *(const ulonglong2*)(ht + (n + 1) * 36);
        ulonglong2 hn1 = *(const ulonglong2*)(ht + (n + 1) * 36 + 4);
        accum_ops(wcur, hc0, hc1, acc);
        wcur = wn; hc0 = hn0; hc1 = hn1;
    }
    accum_ops(wcur, hc0, hc1, acc);

    // ---- streamed rows: LDG rotation + depth-1 h pipeline ----
    const float* hts = ht + (ICC / 4) * 36;
    ulonglong2 sh0 = *(const ulonglong2*)hts;
    ulonglong2 sh1 = *(const ulonglong2*)(hts + 4);
#pragma unroll 6
    for (int i = 0; i < NSMAIN; i++) {
        float4 wv = buf[i % PFD];
        buf[i % PFD] = __ldg((const float4*)(wgx + (i + PFD) * 4 * HH));
        ulonglong2 nh0 = *(const ulonglong2*)(hts + (i + 1) * 36);
        ulonglong2 nh1 = *(const ulonglong2*)(hts + (i + 1) * 36 + 4);
        accum_rws(wv, sh0, sh1, acc);
        sh0 = nh0; sh1 = nh1;
    }
    // tail: consume remaining buffers (h prefetch peeled at the end)
#pragma unroll
    for (int p = 0; p < PFD - 1; p++) {
        ulonglong2 nh0 = *(const ulonglong2*)(hts + (NSMAIN + p + 1) * 36);
        ulonglong2 nh1 = *(const ulonglong2*)(hts + (NSMAIN + p + 1) * 36 + 4);
        accum_rws(buf[p], sh0, sh1, acc);
        sh0 = nh0; sh1 = nh1;
    }
    accum_rws(buf[PFD - 1], sh0, sh1, acc);

    // K-reduction across kq via shuffles
#pragma unroll
    for (int q = 0; q < 16; q++) {
        acc[q] = addf2(acc[q], __shfl_xor_sync(0xffffffffu, acc[q], 8));
        acc[q] = addf2(acc[q], __shfl_xor_sync(0xffffffffu, acc[q], 16));
    }

    float2 blo = unpack2(bq.x), bhi = unpack2(bq.y);
    const float bj[4] = { blo.x, blo.y, bhi.x, bhi.y };
    float vx[4], vy[4];
#pragma unroll
    for (int jj = 0; jj < 4; jj++) {
        float2 v = unpack2(acc[jj * 4 + kq]);
        vx[jj] = elu1(v.x + bj[jj]);
        vy[jj] = elu1(v.y + bj[jj]);
    }

    if (TO_H3P) {
        *(float4*)(hdst + (2 * kq) * 260 + j0q)     = make_float4(vx[0], vx[1], vx[2], vx[3]);
        *(float4*)(hdst + (2 * kq + 1) * 260 + j0q) = make_float4(vy[0], vy[1], vy[2], vy[3]);
    } else {
        float* wb = hdst + 36 * quadg + 2 * kq;
#pragma unroll
        for (int jj = 0; jj < 4; jj++)
            *(u64*)(wb + 8 * jj) = pack2(vx[jj], vy[jj]);
    }
}

__global__ __launch_bounds__(NTHR, 1)
void ode_main(const float* __restrict__ t, const float* __restrict__ x,
              const float* __restrict__ z, const float* __restrict__ event_t,
              const float* __restrict__ z_jump,
              const float* __restrict__ W1, const float* __restrict__ b1,
              const float* __restrict__ W2, const float* __restrict__ b2,
              const float* __restrict__ W3, const float* __restrict__ b3,
              const float* __restrict__ W4, const float* __restrict__ b4,
              float* __restrict__ out)
{
    extern __shared__ float sm[];
    float* w2c  = sm + OFF_W2;
    float* w3c  = sm + OFF_W3;
    float* hA   = sm + OFF_HA;
    float* hB   = sm + OFF_HB;
    float* h3p  = sm + OFF_H3;
    float* w4t  = sm + OFF_W4;
    float* inp  = sm + OFF_INP;
    float* red  = sm + OFF_RED;
    float* zjs  = sm + OFF_ZJ;
    float* evts = sm + OFF_EVT;
    float* b4s  = sm + OFF_B4;
    float* tsh  = sm + OFF_TSH;

    const int tid = threadIdx.x;
    const int b0  = blockIdx.x * 8;

    const int lane = tid & 31, warp = tid >> 5;
    const int quadg = warp * 8 + (lane & 7);
    const int j0q   = quadg * 4;
    const int kq    = lane >> 3;
    const int pr  = warp * 16 + (lane & 15);
    const int j0  = pr * 2;
    const int gq  = lane >> 4;
    const int l1w = 16 * pr + ((pr >> 1) * 4);

    for (int idx = tid; idx < ICC * HH; idx += NTHR) { w2c[idx] = W2[idx]; w3c[idx] = W3[idx]; }
    for (int idx = tid; idx < 8 * HH; idx += NTHR) {
        int k = idx >> 8, i = idx & 255;
        w4t[k * 260 + i] = W4[i * 8 + k];
    }
    if (tid < 8) { evts[tid] = event_t[b0 + tid]; b4s[tid] = b4[tid]; }
    if (tid < 64) { int g = tid >> 3, i = tid & 7; zjs[tid] = z_jump[(b0 + g) * 8 + i]; }
    if (tid == 0) { tsh[0] = t[0]; tsh[1] = t[1]; }

    float zreg = 0.f; size_t zbase = 0;
    if (tid >= 64 && tid < 128) {
        int r = tid - 64, g = r >> 3, i = r & 7;
        zbase = (size_t)(b0 + g) * Tt * 8 + i;
    }
    float treg = 0.f;
    if (tid == 192) treg = t[2];

    if (tid < 64) {
        int k = tid & 7, g = tid >> 3;
        float xv = x[(size_t)(b0 + g) * Tt * 8 + k];
        red[k * 8 + g] = xv;
        inp[HROW(k) + g] = xv;
        out[(size_t)(b0 + g) * Tt * 8 + k] = xv;
    } else if (tid < 128) {
        int r = tid - 64, g = r >> 3, zi = r & 7;
        float z0 = z[zbase];
        red[(8 + zi) * 8 + g] = z0;
        zreg = z[zbase + 8];
    }
    __syncthreads();

    if (tid >= 64 && tid < 128) {
        int r = tid - 64, g = r >> 3, zi = r & 7;
        float v = (tsh[0] >= evts[g]) ? zjs[r] : red[(8 + zi) * 8 + g];
        inp[HROW(8 + zi) + g] = v;
    }

    u64 wxz[16];
    u64 cig[4];
    {
        float ca[2][4];
        float cx = b1[j0], cy = b1[j0 + 1];
#pragma unroll
        for (int gp = 0; gp < 4; gp++) { ca[0][gp] = cx; ca[1][gp] = cy; }
#pragma unroll
        for (int i = 0; i < 16; i++) {
            float2 wa = *(const float2*)&W1[i * HH + j0];
            float2 wb = *(const float2*)&W1[(16 + i) * HH + j0];
            float2 wc = *(const float2*)&W1[(32 + i) * HH + j0];
            wxz[i] = pack2(wb.x + wc.x, wb.y + wc.y);
            float dx = wa.x - wb.x, dy = wa.y - wb.y;
#pragma unroll
            for (int gp = 0; gp < 4; gp++) {
                float a = red[i * 8 + gq * 4 + gp];
                ca[0][gp] = fmaf(a, dx, ca[0][gp]);
                ca[1][gp] = fmaf(a, dy, ca[1][gp]);
            }
        }
#pragma unroll
        for (int j = 0; j < 2; j++)
#pragma unroll
            for (int p = 0; p < 2; p++)
                cig[j * 2 + p] = pack2(ca[j][2 * p], ca[j][2 * p + 1]);
    }
    const ulonglong2 b2q = *(const ulonglong2*)&b2[j0q];
    const ulonglong2 b3q = *(const ulonglong2*)&b3[j0q];

    const int c4 = tid >> 6, r4 = tid & 63, k4 = r4 & 7, g4 = r4 >> 3;
    __syncthreads();

    for (int s = 0; s < Tt - 1; s++) {
        const float t0 = tsh[s & 1];
        const float t1 = tsh[(s + 1) & 1];
        const float dt = t1 - t0;

        // ---- layer 1 (K=16, folded) ----
        {
            u64 acc[4] = { cig[0], cig[1], cig[2], cig[3] };
#pragma unroll
            for (int i = 0; i < 16; i++) {
                ulonglong2 hv = *(const ulonglong2*)(inp + HROW(i) + gq * 4);
                float2 wp = unpack2(wxz[i]);
                u64 wd0 = pack2(wp.x, wp.x), wd1 = pack2(wp.y, wp.y);
                acc[0] = ffma2(hv.x, wd0, acc[0]);
                acc[1] = ffma2(hv.y, wd0, acc[1]);
                acc[2] = ffma2(hv.x, wd1, acc[2]);
                acc[3] = ffma2(hv.y, wd1, acc[3]);
            }
#pragma unroll
            for (int j = 0; j < 2; j++) {
                float2 v0 = unpack2(acc[j * 2]);
                float2 v1 = unpack2(acc[j * 2 + 1]);
                *(float4*)(hA + l1w + 8 * j + gq * 4) =
                    make_float4(elu1(v0.x), elu1(v0.y), elu1(v1.x), elu1(v1.y));
            }
        }
        __syncthreads();

        if (tid == 192) {
            if (s + 2 < Tt) tsh[s & 1] = treg;
            if (s + 3 < Tt) treg = t[s + 3];
        }
        float znext = 0.f;
        if (tid >= 64 && tid < 128 && s + 2 < Tt) znext = z[zbase + (size_t)(s + 2) * 8];

        // ---- layer 2 ----
        biglayerG<false>(w2c, W2, hA, hB, j0q, kq, quadg, b2q);
        __syncthreads();

        // ---- layer 3 ----
        biglayerG<true>(w3c, W3, hB, h3p, j0q, kq, quadg, b3q);
        __syncthreads();

        // ---- layer 4 partials ----
        {
            float p = 0.f;
            const int base = c4 * 64;
            const float* hp = h3p + g4 * 260 + base;
            const float* wp = w4t + k4 * 260 + base;
#pragma unroll
            for (int it = 0; it < 16; it++) {
                float4 hv = *(const float4*)(hp + it * 4);
                float4 wv = *(const float4*)(wp + it * 4);
                p = fmaf(hv.x, wv.x, p); p = fmaf(hv.y, wv.y, p);
                p = fmaf(hv.z, wv.z, p); p = fmaf(hv.w, wv.w, p);
            }
            red[tid] = p;
        }
        __syncthreads();

        // ---- epilogue ----
        if (tid < 64) {
            int k = tid & 7, g = tid >> 3;
            float o = b4s[k] + red[tid] + red[tid + 64] + red[tid + 128] + red[tid + 192];
            float xn = inp[HROW(k) + g] + dt * o;
            inp[HROW(k) + g] = xn;
            out[(size_t)(b0 + g) * Tt * 8 + (size_t)(s + 1) * 8 + k] = xn;
        } else if (tid < 128) {
            int r = tid - 64, g = r >> 3, zi = r & 7;
            float v = (t1 >= evts[g]) ? zjs[r] : zreg;
            inp[HROW(8 + zi) + g] = v;
            zreg = znext;
        }
        __syncthreads();
    }
}

extern "C" void kernel_launch(void* const* d_in, const int* in_sizes, int n_in,
                              void* d_out, int out_size) {
    const float* t       = (const float*)d_in[0];
    const float* x       = (const float*)d_in[1];
    const float* z       = (const float*)d_in[2];
    const float* event_t = (const float*)d_in[3];
    const float* z_jump  = (const float*)d_in[4];
    const float* W1      = (const float*)d_in[5];
    const float* b1      = (const float*)d_in[6];
    const float* W2      = (const float*)d_in[7];
    const float* b2      = (const float*)d_in[8];
    const float* W3      = (const float*)d_in[9];
    const float* b3      = (const float*)d_in[10];
    const float* W4      = (const float*)d_in[11];
    const float* b4      = (const float*)d_in[12];
    float* out = (float*)d_out;

    cudaFuncSetAttribute(ode_main, cudaFuncAttributeMaxDynamicSharedMemorySize, SM_BYTES);

    ode_main<<<NBLK, NTHR, SM_BYTES>>>(t, x, z, event_t, z_jump,
                                       W1, b1, W2, b2, W3, b3, W4, b4, out);
}